// round 16
// baseline (speedup 1.0000x reference)
#include <cuda_runtime.h>
#include <cuda_fp16.h>
#include <stdint.h>

// Problem constants
#define BB 2
#define SS 2048
#define DD 1024
#define HH 16
#define HD 64
#define MM (BB * SS)   // 4096
#define NH (BB * HH * SS * HD)

// fp16 single planes: GEMM inputs + weights (cvt prepass)
__device__ __align__(16) uint16_t g_iq16[MM * DD], g_ik16[MM * DD], g_iv16[MM * DD];
__device__ __align__(16) uint16_t g_wq16[DD * DD], g_wk16[DD * DD];
__device__ __align__(16) uint16_t g_wv16[DD * DD], g_wo16[DD * DD];
// flash inputs, head layout [B,H,S,HD]: Q fp16, K hi/lo fp16, V fp16
__device__ __align__(16) uint16_t g_fq[NH];
__device__ __align__(16) uint16_t g_fkh[NH], g_fkl[NH], g_fv[NH];
// ctx fp16, [B,S,D]
__device__ __align__(16) uint16_t g_cx16[MM * DD];

// ---------------------------------------------------------------------------
// helpers
// ---------------------------------------------------------------------------
__device__ __forceinline__ uint32_t fh2(float a, float b) {
    __half ha = __float2half_rn(a);
    __half hb = __float2half_rn(b);
    return (uint32_t)__half_as_ushort(ha) | ((uint32_t)__half_as_ushort(hb) << 16);
}

__device__ __forceinline__ void fhsplit2(float a, float b, uint32_t& hi, uint32_t& lo) {
    __half ha = __float2half_rn(a);
    __half hb = __float2half_rn(b);
    __half la = __float2half_rn(a - __half2float(ha));
    __half lb = __float2half_rn(b - __half2float(hb));
    hi = (uint32_t)__half_as_ushort(ha) | ((uint32_t)__half_as_ushort(hb) << 16);
    lo = (uint32_t)__half_as_ushort(la) | ((uint32_t)__half_as_ushort(lb) << 16);
}

__device__ __forceinline__ void mma_f16(float (&d)[4], const uint32_t (&a)[4],
                                        uint32_t b0, uint32_t b1) {
    asm volatile(
        "mma.sync.aligned.m16n8k16.row.col.f32.f16.f16.f32 "
        "{%0,%1,%2,%3}, {%4,%5,%6,%7}, {%8,%9}, {%0,%1,%2,%3};\n"
        : "+f"(d[0]), "+f"(d[1]), "+f"(d[2]), "+f"(d[3])
        : "r"(a[0]), "r"(a[1]), "r"(a[2]), "r"(a[3]), "r"(b0), "r"(b1));
}

__device__ __forceinline__ void ldsm4(uint32_t& r0, uint32_t& r1,
                                      uint32_t& r2, uint32_t& r3, uint32_t addr) {
    asm volatile("ldmatrix.sync.aligned.m8n8.x4.shared.b16 {%0,%1,%2,%3}, [%4];\n"
                 : "=r"(r0), "=r"(r1), "=r"(r2), "=r"(r3) : "r"(addr));
}

__device__ __forceinline__ void ldsm4t(uint32_t& r0, uint32_t& r1,
                                       uint32_t& r2, uint32_t& r3, uint32_t addr) {
    asm volatile("ldmatrix.sync.aligned.m8n8.x4.trans.shared.b16 {%0,%1,%2,%3}, [%4];\n"
                 : "=r"(r0), "=r"(r1), "=r"(r2), "=r"(r3) : "r"(addr));
}

__device__ __forceinline__ void cp_async16(void* sm, const void* g) {
    uint32_t a = (uint32_t)__cvta_generic_to_shared(sm);
    asm volatile("cp.async.cg.shared.global [%0], [%1], 16;\n" :: "r"(a), "l"(g));
}
__device__ __forceinline__ void cp_commit() {
    asm volatile("cp.async.commit_group;\n");
}

// ---------------------------------------------------------------------------
// Kernel 0: convert inputs + weights to fp16. grid = (512, 7)
// ---------------------------------------------------------------------------
__global__ __launch_bounds__(256)
void cvt_f16_all(const float* __restrict__ q, const float* __restrict__ k,
                 const float* __restrict__ v,
                 const float* __restrict__ wq, const float* __restrict__ wk,
                 const float* __restrict__ wv, const float* __restrict__ wo) {
    const int y = blockIdx.y;
    const float* src;
    uint16_t* dst;
    int n4;
    switch (y) {
        case 0: src = q;  dst = g_iq16; n4 = MM * DD / 4; break;
        case 1: src = k;  dst = g_ik16; n4 = MM * DD / 4; break;
        case 2: src = v;  dst = g_iv16; n4 = MM * DD / 4; break;
        case 3: src = wq; dst = g_wq16; n4 = DD * DD / 4; break;
        case 4: src = wk; dst = g_wk16; n4 = DD * DD / 4; break;
        case 5: src = wv; dst = g_wv16; n4 = DD * DD / 4; break;
        default: src = wo; dst = g_wo16; n4 = DD * DD / 4; break;
    }
    for (int i = blockIdx.x * blockDim.x + threadIdx.x; i < n4;
         i += gridDim.x * blockDim.x) {
        float4 f = ((const float4*)src)[i];
        uint2 u;
        u.x = fh2(f.x, f.y);
        u.y = fh2(f.z, f.w);
        ((uint2*)dst)[i] = u;
    }
}

// ---------------------------------------------------------------------------
// fp16 GEMM core: C[m,n] = sum_k X[m,k]*W[n,k], single-fp16 operands.
// Block 64x128, BK=32, 128 threads (4 warps x 32x64), 2-stage cp.async.
// ---------------------------------------------------------------------------
#define BKP 40               // fp16 elems per smem row (80 B)
#define G_A 0                // elem offsets within a stage
#define G_B 2560             // 64*40
#define G_STAGE 7680         // elems per stage (A 2560 + B 5120)
#define PJ_SMEM (2 * G_STAGE * 2)   // 30720 bytes

__device__ __forceinline__ void gemm_issue(uint16_t* st,
                                           const uint16_t* __restrict__ X,
                                           const uint16_t* __restrict__ W,
                                           int m0, int n0, int k0, int tid) {
#pragma unroll
    for (int r = 0; r < 2; r++) {            // A: 64 rows x 4 chunks
        const int idx = tid + r * 128;
        const int row = idx >> 2;
        const int c = (idx & 3) * 8;
        cp_async16(st + G_A + row * BKP + c, X + (size_t)(m0 + row) * DD + k0 + c);
    }
#pragma unroll
    for (int r = 0; r < 4; r++) {            // B: 128 rows x 4 chunks
        const int idx = tid + r * 128;
        const int row = idx >> 2;
        const int c = (idx & 3) * 8;
        cp_async16(st + G_B + row * BKP + c, W + (size_t)(n0 + row) * DD + k0 + c);
    }
    cp_commit();
}

__device__ __forceinline__ void gemm_tile(const uint16_t* __restrict__ X,
                                          const uint16_t* __restrict__ W,
                                          uint16_t* sm, int m0, int n0,
                                          float (&acc)[2][8][4]) {
    const int tid  = threadIdx.x;
    const int warp = tid >> 5;
    const int lane = tid & 31;
    const int wm = (warp & 1) * 32;
    const int wn = (warp >> 1) * 64;

    const int sel = lane >> 3;
    const int l7  = lane & 7;
    const int a_row = (sel & 1) * 8 + l7;
    const int a_kb  = (sel >> 1) * 16;       // bytes
    const int b_row = (sel >> 1) * 8 + l7;
    const int b_kb  = (sel & 1) * 16;

    const uint32_t sa = (uint32_t)__cvta_generic_to_shared(sm);
    uint32_t aAddr[2][2], bAddr[2][4];
#pragma unroll
    for (int s = 0; s < 2; s++) {
        const uint32_t sb = sa + s * (G_STAGE * 2);
#pragma unroll
        for (int mi = 0; mi < 2; mi++)
            aAddr[s][mi] = sb + (G_A + (wm + mi * 16 + a_row) * BKP) * 2 + a_kb;
#pragma unroll
        for (int np = 0; np < 4; np++)
            bAddr[s][np] = sb + (G_B + (wn + np * 16 + b_row) * BKP) * 2 + b_kb;
    }

    gemm_issue(sm,           X, W, m0, n0, 0, tid);
    gemm_issue(sm + G_STAGE, X, W, m0, n0, 32, tid);

    int s = 0;
    for (int k0 = 0; k0 < DD; k0 += 32, s ^= 1) {
        if (k0 + 32 < DD) asm volatile("cp.async.wait_group 1;\n");
        else              asm volatile("cp.async.wait_group 0;\n");
        __syncthreads();

#pragma unroll
        for (int ks = 0; ks < 2; ks++) {     // 2 k16-steps per BK=32
            const uint32_t ko = ks * 32;     // 16 fp16 = 32 bytes
            uint32_t af[2][4];
#pragma unroll
            for (int mi = 0; mi < 2; mi++)
                ldsm4(af[mi][0], af[mi][1], af[mi][2], af[mi][3], aAddr[s][mi] + ko);
#pragma unroll
            for (int np = 0; np < 4; np++) {
                uint32_t b0, b1, b2, b3;
                ldsm4(b0, b1, b2, b3, bAddr[s][np] + ko);
#pragma unroll
                for (int mi = 0; mi < 2; mi++) {
                    mma_f16(acc[mi][2 * np],     af[mi], b0, b1);
                    mma_f16(acc[mi][2 * np + 1], af[mi], b2, b3);
                }
            }
        }
        __syncthreads();
        if (k0 + 64 < DD)
            gemm_issue(sm + (s ? G_STAGE : 0), X, W, m0, n0, k0 + 64, tid);
    }
}

// ---------------------------------------------------------------------------
// Kernel 1: QKV projection. grid = (8, 64, 3), 128 threads.
// Emits Q fp16, K fp16 hi/lo planes, V fp16 in head layout [B,H,S,HD].
// ---------------------------------------------------------------------------
__global__ __launch_bounds__(128, 4)
void qkv_proj_tc(const float* __restrict__ bq, const float* __restrict__ bk,
                 const float* __restrict__ bv) {
    extern __shared__ uint16_t gsm[];
    const int which = blockIdx.z;
    const uint16_t* X = (which == 0) ? g_iq16 : (which == 1) ? g_ik16 : g_iv16;
    const uint16_t* W = (which == 0) ? g_wq16 : (which == 1) ? g_wk16 : g_wv16;
    const float* bias = (which == 0) ? bq : (which == 1) ? bk : bv;

    float acc[2][8][4];
#pragma unroll
    for (int mi = 0; mi < 2; mi++)
#pragma unroll
        for (int ni = 0; ni < 8; ni++)
#pragma unroll
            for (int r = 0; r < 4; r++) acc[mi][ni][r] = 0.f;

    const int m0 = blockIdx.y * 64;
    const int n0 = blockIdx.x * 128;
    gemm_tile(X, W, gsm, m0, n0, acc);

    const int tid  = threadIdx.x;
    const int warp = tid >> 5;
    const int lane = tid & 31;
    const int g = lane >> 2, t = lane & 3;
    const int wm = (warp & 1) * 32;
    const int wn = (warp >> 1) * 64;

#pragma unroll
    for (int mi = 0; mi < 2; mi++) {
#pragma unroll
        for (int rr = 0; rr < 2; rr++) {
            const int m = m0 + wm + mi * 16 + rr * 8 + g;
            const int b = m >> 11;
            const int s = m & 2047;
#pragma unroll
            for (int ni = 0; ni < 8; ni++) {
                const int n = n0 + wn + ni * 8 + t * 2;
                const int h = n >> 6;
                const int d = n & 63;
                const size_t off = ((size_t)(b * HH + h) * SS + s) * HD + d;
                float v0 = acc[mi][ni][rr * 2 + 0] + bias[n];
                float v1 = acc[mi][ni][rr * 2 + 1] + bias[n + 1];
                if (which == 0) {
                    *(uint32_t*)&g_fq[off] = fh2(v0, v1);
                } else if (which == 1) {
                    uint32_t hi, lo;
                    fhsplit2(v0, v1, hi, lo);
                    *(uint32_t*)&g_fkh[off] = hi;
                    *(uint32_t*)&g_fkl[off] = lo;
                } else {
                    *(uint32_t*)&g_fv[off] = fh2(v0, v1);
                }
            }
        }
    }
}

// ---------------------------------------------------------------------------
// Kernel 3: output projection. X = g_cx16. grid = (8, 64), 128 threads.
// ---------------------------------------------------------------------------
__global__ __launch_bounds__(128, 4)
void out_proj_tc(const float* __restrict__ bo, float* __restrict__ out) {
    extern __shared__ uint16_t gsm[];
    float acc[2][8][4];
#pragma unroll
    for (int mi = 0; mi < 2; mi++)
#pragma unroll
        for (int ni = 0; ni < 8; ni++)
#pragma unroll
            for (int r = 0; r < 4; r++) acc[mi][ni][r] = 0.f;

    const int m0 = blockIdx.y * 64;
    const int n0 = blockIdx.x * 128;
    gemm_tile(g_cx16, g_wo16, gsm, m0, n0, acc);

    const int tid  = threadIdx.x;
    const int warp = tid >> 5;
    const int lane = tid & 31;
    const int g = lane >> 2, t = lane & 3;
    const int wm = (warp & 1) * 32;
    const int wn = (warp >> 1) * 64;

#pragma unroll
    for (int mi = 0; mi < 2; mi++) {
#pragma unroll
        for (int rr = 0; rr < 2; rr++) {
            const int m = m0 + wm + mi * 16 + rr * 8 + g;
#pragma unroll
            for (int ni = 0; ni < 8; ni++) {
                const int n = n0 + wn + ni * 8 + t * 2;
                float2 v;
                v.x = acc[mi][ni][rr * 2 + 0] + bo[n];
                v.y = acc[mi][ni][rr * 2 + 1] + bo[n + 1];
                *(float2*)&out[(size_t)m * DD + n] = v;
            }
        }
    }
}

// ---------------------------------------------------------------------------
// Kernel 2: fp16 causal flash attention (R15 config + per-n-block live_p skip).
// CTA = 128 q-rows x (head, batch), 8 warps x m16, KV tiles of 64.
// QK^T = q*(khi+klo); PV = p*v. For each warp+tile, only the first live_p
// of 4 n-blocks (16 cols each) contain unmasked entries; the rest are skipped
// exactly (their exp underflows to 0.0 in the reference path).
// Barriers/prefetch/wait stay outside all conditionals; predicates warp-uniform.
// SMEM (144B rows): Q 0 / KH 18432 / KL 27648 / V 36864 (2 bufs)
// ---------------------------------------------------------------------------
#define FQ  0
#define FKH 18432
#define FKL 27648
#define FV  36864
#define FA_SMEM 55296

__global__ __launch_bounds__(256, 2)
void flash_attn_tc() {
    extern __shared__ char fsm[];
    const uint32_t sb = (uint32_t)__cvta_generic_to_shared(fsm);

    const int qt = (gridDim.x - 1) - blockIdx.x;  // heavy tiles first
    const int h  = blockIdx.y;
    const int b  = blockIdx.z;
    const int tid  = threadIdx.x;
    const int warp = tid >> 5;
    const int lane = tid & 31;
    const int g = lane >> 2;
    const int t = lane & 3;
    const int wm = warp * 16;
    const int q0 = qt * 128;

    const size_t hb = (size_t)(b * HH + h) * SS * HD;
    const uint16_t* __restrict__ Qg = g_fq  + hb;
    const uint16_t* __restrict__ Hg = g_fkh + hb;
    const uint16_t* __restrict__ Lg = g_fkl + hb;
    const uint16_t* __restrict__ Vg = g_fv  + hb;

    const int sel = lane >> 3;
    const int l7  = lane & 7;
    // A-frag (Q / P): sel&1 -> +8 rows, sel>>1 -> +16B k
    const uint32_t aOff = ((wm + (sel & 1) * 8 + l7) * 144) + (sel >> 1) * 16;
    const uint32_t qAddr = sb + FQ + aOff;
    // K B-frag: sel>>1 -> +8 n-rows, sel&1 -> +16B k
    const uint32_t kOff = (((sel >> 1) * 8 + l7) * 144) + (sel & 1) * 16;
    const uint32_t kAddrH = sb + FKH + kOff;
    const uint32_t kAddrL = sb + FKL + kOff;
    // V trans B-frag: sel&1 -> +8 k-rows, sel>>1 -> +16B n
    const uint32_t vBase = sb + FV + (((sel & 1) * 8 + l7) * 144) + (sel >> 1) * 16;

    // ---- prologue: K/V tile 0, then Q ----
    {
#pragma unroll
        for (int r = 0; r < 4; r++) {        // K hi+lo: 1024 chunks
            const int idx = tid + r * 256;
            const int plane = idx >> 9;
            const int rem = idx & 511;
            const int row = rem >> 3;
            const int c = (rem & 7) * 8;
            const uint16_t* src = plane ? Lg : Hg;
            cp_async16(fsm + (plane ? FKL : FKH) + row * 144 + c * 2,
                       src + (size_t)row * HD + c);
        }
#pragma unroll
        for (int r = 0; r < 2; r++) {        // V buf0: 512 chunks
            const int idx = tid + r * 256;
            const int row = idx >> 3;
            const int c = (idx & 7) * 8;
            cp_async16(fsm + FV + row * 144 + c * 2, Vg + (size_t)row * HD + c);
        }
        cp_commit();
#pragma unroll
        for (int r = 0; r < 4; r++) {        // Q: 1024 chunks
            const int idx = tid + r * 256;
            const int row = idx >> 3;
            const int c = (idx & 7) * 8;
            cp_async16(fsm + FQ + row * 144 + c * 2,
                       Qg + (size_t)(q0 + row) * HD + c);
        }
        cp_commit();
        asm volatile("cp.async.wait_group 0;\n");
    }
    __syncthreads();

    // pin Q fragments in registers: 4 k16-steps
    uint32_t qf[4][4];
#pragma unroll
    for (int ks = 0; ks < 4; ks++)
        ldsm4(qf[ks][0], qf[ks][1], qf[ks][2], qf[ks][3], qAddr + ks * 32);
    __syncthreads();   // Q smem dead; Ps may overwrite

    float oacc[8][4];
#pragma unroll
    for (int ni = 0; ni < 8; ni++)
#pragma unroll
        for (int r = 0; r < 4; r++) oacc[ni][r] = 0.f;
    float m0r = -1e30f, m1r = -1e30f, l0r = 0.f, l1r = 0.f;

    const float scale = 0.125f;
    const int ntiles = 2 * qt + 2;
    const int qmax = q0 + wm + 15;   // warp's highest q row

    for (int tt = 0; tt < ntiles; tt++) {
        const int k0 = tt * 64;
        const int buf = tt & 1;
        // number of live 16-column n-blocks for this warp+tile (warp-uniform)
        const int dcol = qmax - k0;
        const int live_p = (dcol < 0) ? 0 : ((dcol >> 4) + 1 < 4 ? (dcol >> 4) + 1 : 4);
        const bool active = live_p > 0;

        // ---- S = q*(khi + klo) (live n-blocks only) ----
        float sacc[8][4];
        if (active) {
#pragma unroll
            for (int ni = 0; ni < 8; ni++)
#pragma unroll
                for (int r = 0; r < 4; r++) sacc[ni][r] = 0.f;

#pragma unroll
            for (int ks = 0; ks < 4; ks++) {
                const uint32_t ko = ks * 32;
#pragma unroll
                for (int p = 0; p < 4; p++) {
                    if (p < live_p) {
                        uint32_t h0, h1, h2, h3, l0, l1, l2, l3;
                        ldsm4(h0, h1, h2, h3, kAddrH + p * 2304 + ko);
                        ldsm4(l0, l1, l2, l3, kAddrL + p * 2304 + ko);
                        mma_f16(sacc[2 * p],     qf[ks], h0, h1);
                        mma_f16(sacc[2 * p],     qf[ks], l0, l1);
                        mma_f16(sacc[2 * p + 1], qf[ks], h2, h3);
                        mma_f16(sacc[2 * p + 1], qf[ks], l2, l3);
                    }
                }
            }
        }
        __syncthreads();   // K readers done before prefetch overwrites

        // ---- prefetch K/V for tile tt+1 (overlaps softmax + PV) ----
        if (tt + 1 < ntiles) {
            const int kn = (tt + 1) * 64;
            const int nbuf = (tt + 1) & 1;
#pragma unroll
            for (int r = 0; r < 4; r++) {
                const int idx = tid + r * 256;
                const int plane = idx >> 9;
                const int rem = idx & 511;
                const int row = rem >> 3;
                const int c = (rem & 7) * 8;
                const uint16_t* src = plane ? Lg : Hg;
                cp_async16(fsm + (plane ? FKL : FKH) + row * 144 + c * 2,
                           src + (size_t)(kn + row) * HD + c);
            }
#pragma unroll
            for (int r = 0; r < 2; r++) {
                const int idx = tid + r * 256;
                const int row = idx >> 3;
                const int c = (idx & 7) * 8;
                cp_async16(fsm + FV + nbuf * 9216 + row * 144 + c * 2,
                           Vg + (size_t)(kn + row) * HD + c);
            }
            cp_commit();
        }

        if (active) {
            // ---- scale + causal mask (live blocks only) ----
            const bool need_mask = (tt >= ntiles - 2);
            const int qi0 = q0 + wm + g;
            const int qi1 = qi0 + 8;
#pragma unroll
            for (int ni = 0; ni < 8; ni++) {
                if ((ni >> 1) < live_p) {
                    const int c0 = k0 + ni * 8 + 2 * t;
                    sacc[ni][0] *= scale; sacc[ni][1] *= scale;
                    sacc[ni][2] *= scale; sacc[ni][3] *= scale;
                    if (need_mask) {
                        if (c0 > qi0)     sacc[ni][0] -= 1e9f;
                        if (c0 + 1 > qi0) sacc[ni][1] -= 1e9f;
                        if (c0 > qi1)     sacc[ni][2] -= 1e9f;
                        if (c0 + 1 > qi1) sacc[ni][3] -= 1e9f;
                    }
                }
            }

            // ---- online softmax (live blocks only) ----
            float mx0 = -1e30f, mx1 = -1e30f;
#pragma unroll
            for (int ni = 0; ni < 8; ni++) {
                if ((ni >> 1) < live_p) {
                    mx0 = fmaxf(mx0, fmaxf(sacc[ni][0], sacc[ni][1]));
                    mx1 = fmaxf(mx1, fmaxf(sacc[ni][2], sacc[ni][3]));
                }
            }
            mx0 = fmaxf(mx0, __shfl_xor_sync(0xffffffffu, mx0, 1));
            mx0 = fmaxf(mx0, __shfl_xor_sync(0xffffffffu, mx0, 2));
            mx1 = fmaxf(mx1, __shfl_xor_sync(0xffffffffu, mx1, 1));
            mx1 = fmaxf(mx1, __shfl_xor_sync(0xffffffffu, mx1, 2));

            const float mn0 = fmaxf(m0r, mx0);
            const float mn1 = fmaxf(m1r, mx1);
            const float al0 = __expf(m0r - mn0);
            const float al1 = __expf(m1r - mn1);
            float s0 = 0.f, s1 = 0.f;
#pragma unroll
            for (int ni = 0; ni < 8; ni++) {
                if ((ni >> 1) < live_p) {
                    float p0 = __expf(sacc[ni][0] - mn0);
                    float p1 = __expf(sacc[ni][1] - mn0);
                    float p2 = __expf(sacc[ni][2] - mn1);
                    float p3 = __expf(sacc[ni][3] - mn1);
                    s0 += p0 + p1; s1 += p2 + p3;
                    const uint32_t cby = (uint32_t)(ni * 8 + 2 * t) * 2;
                    *(uint32_t*)(fsm + FQ + (wm + g)     * 144 + cby) = fh2(p0, p1);
                    *(uint32_t*)(fsm + FQ + (wm + g + 8) * 144 + cby) = fh2(p2, p3);
                }
            }
            s0 += __shfl_xor_sync(0xffffffffu, s0, 1);
            s0 += __shfl_xor_sync(0xffffffffu, s0, 2);
            s1 += __shfl_xor_sync(0xffffffffu, s1, 1);
            s1 += __shfl_xor_sync(0xffffffffu, s1, 2);
            l0r = l0r * al0 + s0;
            l1r = l1r * al1 + s1;
            m0r = mn0; m1r = mn1;
#pragma unroll
            for (int ni = 0; ni < 8; ni++) {
                oacc[ni][0] *= al0; oacc[ni][1] *= al0;
                oacc[ni][2] *= al1; oacc[ni][3] *= al1;
            }
            __syncwarp();   // Ps rows per-warp: write->read within warp

            // ---- O += P @ V (k16-steps with live P columns only) ----
#pragma unroll
            for (int ks = 0; ks < 4; ks++) {
                if (ks < live_p) {
                    uint32_t pf[4];
                    ldsm4(pf[0], pf[1], pf[2], pf[3], qAddr + ks * 32);
                    const uint32_t vrow = vBase + buf * 9216 + ks * 2304;
#pragma unroll
                    for (int p = 0; p < 4; p++) {
                        uint32_t v0, v1, v2, v3;
                        ldsm4t(v0, v1, v2, v3, vrow + p * 32);
                        mma_f16(oacc[2 * p],     pf, v0, v1);
                        mma_f16(oacc[2 * p + 1], pf, v2, v3);
                    }
                }
            }
        }
        if (tt + 1 < ntiles) asm volatile("cp.async.wait_group 0;\n");
        __syncthreads();   // publish next K/V; retire Ps/V reads
    }

    // ---- normalize + store ctx fp16 [B,S,D] ----
    const float inv0 = 1.0f / l0r;
    const float inv1 = 1.0f / l1r;
    const int r0 = q0 + wm + g;
    const size_t o0 = ((size_t)(b * SS + r0))     * DD + h * HD;
    const size_t o1 = ((size_t)(b * SS + r0 + 8)) * DD + h * HD;
#pragma unroll
    for (int ni = 0; ni < 8; ni++) {
        const int c = ni * 8 + 2 * t;
        *(uint32_t*)&g_cx16[o0 + c] = fh2(oacc[ni][0] * inv0, oacc[ni][1] * inv0);
        *(uint32_t*)&g_cx16[o1 + c] = fh2(oacc[ni][2] * inv1, oacc[ni][3] * inv1);
    }
}

// ---------------------------------------------------------------------------
extern "C" void kernel_launch(void* const* d_in, const int* in_sizes, int n_in,
                              void* d_out, int out_size) {
    const float* query = (const float*)d_in[0];
    const float* key   = (const float*)d_in[1];
    const float* value = (const float*)d_in[2];
    // d_in[3] = mask (causal; applied analytically in-kernel)
    const float* Wq = (const float*)d_in[4];
    const float* bq = (const float*)d_in[5];
    const float* Wk = (const float*)d_in[6];
    const float* bk = (const float*)d_in[7];
    const float* Wv = (const float*)d_in[8];
    const float* bv = (const float*)d_in[9];
    const float* Wo = (const float*)d_in[10];
    const float* bo = (const float*)d_in[11];
    float* out = (float*)d_out;

    cudaFuncSetAttribute(flash_attn_tc,
                         cudaFuncAttributeMaxDynamicSharedMemorySize, FA_SMEM);
    cudaFuncSetAttribute(qkv_proj_tc,
                         cudaFuncAttributeMaxDynamicSharedMemorySize, PJ_SMEM);
    cudaFuncSetAttribute(out_proj_tc,
                         cudaFuncAttributeMaxDynamicSharedMemorySize, PJ_SMEM);

    dim3 gcvt(512, 7);
    cvt_f16_all<<<gcvt, 256>>>(query, key, value, Wq, Wk, Wv, Wo);

    dim3 gproj(DD / 128, MM / 64, 3);
    qkv_proj_tc<<<gproj, 128, PJ_SMEM>>>(bq, bk, bv);

    dim3 gfa(SS / 128, HH, BB);
    flash_attn_tc<<<gfa, 256, FA_SMEM>>>();

    dim3 gout(DD / 128, MM / 64);
    out_proj_tc<<<gout, 128, PJ_SMEM>>>(bo, out);
}

// round 17
// speedup vs baseline: 1.0445x; 1.0445x over previous
#include <cuda_runtime.h>
#include <cuda_fp16.h>
#include <stdint.h>

// Problem constants
#define BB 2
#define SS 2048
#define DD 1024
#define HH 16
#define HD 64
#define MM (BB * SS)   // 4096
#define NH (BB * HH * SS * HD)

// fp16 single planes: GEMM inputs + weights (cvt prepass)
__device__ __align__(16) uint16_t g_iq16[MM * DD], g_ik16[MM * DD], g_iv16[MM * DD];
__device__ __align__(16) uint16_t g_wq16[DD * DD], g_wk16[DD * DD];
__device__ __align__(16) uint16_t g_wv16[DD * DD], g_wo16[DD * DD];
// flash inputs, head layout [B,H,S,HD]: Q fp16, K hi/lo fp16, V fp16
__device__ __align__(16) uint16_t g_fq[NH];
__device__ __align__(16) uint16_t g_fkh[NH], g_fkl[NH], g_fv[NH];
// ctx fp16, [B,S,D]
__device__ __align__(16) uint16_t g_cx16[MM * DD];

// ---------------------------------------------------------------------------
// helpers
// ---------------------------------------------------------------------------
__device__ __forceinline__ uint32_t fh2(float a, float b) {
    __half ha = __float2half_rn(a);
    __half hb = __float2half_rn(b);
    return (uint32_t)__half_as_ushort(ha) | ((uint32_t)__half_as_ushort(hb) << 16);
}

__device__ __forceinline__ void fhsplit2(float a, float b, uint32_t& hi, uint32_t& lo) {
    __half ha = __float2half_rn(a);
    __half hb = __float2half_rn(b);
    __half la = __float2half_rn(a - __half2float(ha));
    __half lb = __float2half_rn(b - __half2float(hb));
    hi = (uint32_t)__half_as_ushort(ha) | ((uint32_t)__half_as_ushort(hb) << 16);
    lo = (uint32_t)__half_as_ushort(la) | ((uint32_t)__half_as_ushort(lb) << 16);
}

__device__ __forceinline__ void mma_f16(float (&d)[4], const uint32_t (&a)[4],
                                        uint32_t b0, uint32_t b1) {
    asm volatile(
        "mma.sync.aligned.m16n8k16.row.col.f32.f16.f16.f32 "
        "{%0,%1,%2,%3}, {%4,%5,%6,%7}, {%8,%9}, {%0,%1,%2,%3};\n"
        : "+f"(d[0]), "+f"(d[1]), "+f"(d[2]), "+f"(d[3])
        : "r"(a[0]), "r"(a[1]), "r"(a[2]), "r"(a[3]), "r"(b0), "r"(b1));
}

__device__ __forceinline__ void ldsm4(uint32_t& r0, uint32_t& r1,
                                      uint32_t& r2, uint32_t& r3, uint32_t addr) {
    asm volatile("ldmatrix.sync.aligned.m8n8.x4.shared.b16 {%0,%1,%2,%3}, [%4];\n"
                 : "=r"(r0), "=r"(r1), "=r"(r2), "=r"(r3) : "r"(addr));
}

__device__ __forceinline__ void ldsm4t(uint32_t& r0, uint32_t& r1,
                                       uint32_t& r2, uint32_t& r3, uint32_t addr) {
    asm volatile("ldmatrix.sync.aligned.m8n8.x4.trans.shared.b16 {%0,%1,%2,%3}, [%4];\n"
                 : "=r"(r0), "=r"(r1), "=r"(r2), "=r"(r3) : "r"(addr));
}

__device__ __forceinline__ void cp_async16(void* sm, const void* g) {
    uint32_t a = (uint32_t)__cvta_generic_to_shared(sm);
    asm volatile("cp.async.cg.shared.global [%0], [%1], 16;\n" :: "r"(a), "l"(g));
}
__device__ __forceinline__ void cp_commit() {
    asm volatile("cp.async.commit_group;\n");
}

// ---------------------------------------------------------------------------
// Kernel 0: convert inputs + weights to fp16. grid = (512, 7)
// ---------------------------------------------------------------------------
__global__ __launch_bounds__(256)
void cvt_f16_all(const float* __restrict__ q, const float* __restrict__ k,
                 const float* __restrict__ v,
                 const float* __restrict__ wq, const float* __restrict__ wk,
                 const float* __restrict__ wv, const float* __restrict__ wo) {
    const int y = blockIdx.y;
    const float* src;
    uint16_t* dst;
    int n4;
    switch (y) {
        case 0: src = q;  dst = g_iq16; n4 = MM * DD / 4; break;
        case 1: src = k;  dst = g_ik16; n4 = MM * DD / 4; break;
        case 2: src = v;  dst = g_iv16; n4 = MM * DD / 4; break;
        case 3: src = wq; dst = g_wq16; n4 = DD * DD / 4; break;
        case 4: src = wk; dst = g_wk16; n4 = DD * DD / 4; break;
        case 5: src = wv; dst = g_wv16; n4 = DD * DD / 4; break;
        default: src = wo; dst = g_wo16; n4 = DD * DD / 4; break;
    }
    for (int i = blockIdx.x * blockDim.x + threadIdx.x; i < n4;
         i += gridDim.x * blockDim.x) {
        float4 f = ((const float4*)src)[i];
        uint2 u;
        u.x = fh2(f.x, f.y);
        u.y = fh2(f.z, f.w);
        ((uint2*)dst)[i] = u;
    }
}

// ---------------------------------------------------------------------------
// fp16 GEMM core: C[m,n] = sum_k X[m,k]*W[n,k], single-fp16 operands.
// Block 64x128, BK=32, 128 threads (4 warps x 32x64), 2-stage cp.async.
// ---------------------------------------------------------------------------
#define BKP 40               // fp16 elems per smem row (80 B)
#define G_A 0                // elem offsets within a stage
#define G_B 2560             // 64*40
#define G_STAGE 7680         // elems per stage (A 2560 + B 5120)
#define PJ_SMEM (2 * G_STAGE * 2)   // 30720 bytes

__device__ __forceinline__ void gemm_issue(uint16_t* st,
                                           const uint16_t* __restrict__ X,
                                           const uint16_t* __restrict__ W,
                                           int m0, int n0, int k0, int tid) {
#pragma unroll
    for (int r = 0; r < 2; r++) {            // A: 64 rows x 4 chunks
        const int idx = tid + r * 128;
        const int row = idx >> 2;
        const int c = (idx & 3) * 8;
        cp_async16(st + G_A + row * BKP + c, X + (size_t)(m0 + row) * DD + k0 + c);
    }
#pragma unroll
    for (int r = 0; r < 4; r++) {            // B: 128 rows x 4 chunks
        const int idx = tid + r * 128;
        const int row = idx >> 2;
        const int c = (idx & 3) * 8;
        cp_async16(st + G_B + row * BKP + c, W + (size_t)(n0 + row) * DD + k0 + c);
    }
    cp_commit();
}

__device__ __forceinline__ void gemm_tile(const uint16_t* __restrict__ X,
                                          const uint16_t* __restrict__ W,
                                          uint16_t* sm, int m0, int n0,
                                          float (&acc)[2][8][4]) {
    const int tid  = threadIdx.x;
    const int warp = tid >> 5;
    const int lane = tid & 31;
    const int wm = (warp & 1) * 32;
    const int wn = (warp >> 1) * 64;

    const int sel = lane >> 3;
    const int l7  = lane & 7;
    const int a_row = (sel & 1) * 8 + l7;
    const int a_kb  = (sel >> 1) * 16;       // bytes
    const int b_row = (sel >> 1) * 8 + l7;
    const int b_kb  = (sel & 1) * 16;

    const uint32_t sa = (uint32_t)__cvta_generic_to_shared(sm);
    uint32_t aAddr[2][2], bAddr[2][4];
#pragma unroll
    for (int s = 0; s < 2; s++) {
        const uint32_t sb = sa + s * (G_STAGE * 2);
#pragma unroll
        for (int mi = 0; mi < 2; mi++)
            aAddr[s][mi] = sb + (G_A + (wm + mi * 16 + a_row) * BKP) * 2 + a_kb;
#pragma unroll
        for (int np = 0; np < 4; np++)
            bAddr[s][np] = sb + (G_B + (wn + np * 16 + b_row) * BKP) * 2 + b_kb;
    }

    gemm_issue(sm,           X, W, m0, n0, 0, tid);
    gemm_issue(sm + G_STAGE, X, W, m0, n0, 32, tid);

    int s = 0;
    for (int k0 = 0; k0 < DD; k0 += 32, s ^= 1) {
        if (k0 + 32 < DD) asm volatile("cp.async.wait_group 1;\n");
        else              asm volatile("cp.async.wait_group 0;\n");
        __syncthreads();

#pragma unroll
        for (int ks = 0; ks < 2; ks++) {     // 2 k16-steps per BK=32
            const uint32_t ko = ks * 32;     // 16 fp16 = 32 bytes
            uint32_t af[2][4];
#pragma unroll
            for (int mi = 0; mi < 2; mi++)
                ldsm4(af[mi][0], af[mi][1], af[mi][2], af[mi][3], aAddr[s][mi] + ko);
#pragma unroll
            for (int np = 0; np < 4; np++) {
                uint32_t b0, b1, b2, b3;
                ldsm4(b0, b1, b2, b3, bAddr[s][np] + ko);
#pragma unroll
                for (int mi = 0; mi < 2; mi++) {
                    mma_f16(acc[mi][2 * np],     af[mi], b0, b1);
                    mma_f16(acc[mi][2 * np + 1], af[mi], b2, b3);
                }
            }
        }
        __syncthreads();
        if (k0 + 64 < DD)
            gemm_issue(sm + (s ? G_STAGE : 0), X, W, m0, n0, k0 + 64, tid);
    }
}

// ---------------------------------------------------------------------------
// Kernel 1: QKV projection. grid = (8, 64, 3), 128 threads.
// Emits Q fp16, K fp16 hi/lo planes, V fp16 in head layout [B,H,S,HD].
// ---------------------------------------------------------------------------
__global__ __launch_bounds__(128, 4)
void qkv_proj_tc(const float* __restrict__ bq, const float* __restrict__ bk,
                 const float* __restrict__ bv) {
    extern __shared__ uint16_t gsm[];
    const int which = blockIdx.z;
    const uint16_t* X = (which == 0) ? g_iq16 : (which == 1) ? g_ik16 : g_iv16;
    const uint16_t* W = (which == 0) ? g_wq16 : (which == 1) ? g_wk16 : g_wv16;
    const float* bias = (which == 0) ? bq : (which == 1) ? bk : bv;

    float acc[2][8][4];
#pragma unroll
    for (int mi = 0; mi < 2; mi++)
#pragma unroll
        for (int ni = 0; ni < 8; ni++)
#pragma unroll
            for (int r = 0; r < 4; r++) acc[mi][ni][r] = 0.f;

    const int m0 = blockIdx.y * 64;
    const int n0 = blockIdx.x * 128;
    gemm_tile(X, W, gsm, m0, n0, acc);

    const int tid  = threadIdx.x;
    const int warp = tid >> 5;
    const int lane = tid & 31;
    const int g = lane >> 2, t = lane & 3;
    const int wm = (warp & 1) * 32;
    const int wn = (warp >> 1) * 64;

#pragma unroll
    for (int mi = 0; mi < 2; mi++) {
#pragma unroll
        for (int rr = 0; rr < 2; rr++) {
            const int m = m0 + wm + mi * 16 + rr * 8 + g;
            const int b = m >> 11;
            const int s = m & 2047;
#pragma unroll
            for (int ni = 0; ni < 8; ni++) {
                const int n = n0 + wn + ni * 8 + t * 2;
                const int h = n >> 6;
                const int d = n & 63;
                const size_t off = ((size_t)(b * HH + h) * SS + s) * HD + d;
                float v0 = acc[mi][ni][rr * 2 + 0] + bias[n];
                float v1 = acc[mi][ni][rr * 2 + 1] + bias[n + 1];
                if (which == 0) {
                    *(uint32_t*)&g_fq[off] = fh2(v0, v1);
                } else if (which == 1) {
                    uint32_t hi, lo;
                    fhsplit2(v0, v1, hi, lo);
                    *(uint32_t*)&g_fkh[off] = hi;
                    *(uint32_t*)&g_fkl[off] = lo;
                } else {
                    *(uint32_t*)&g_fv[off] = fh2(v0, v1);
                }
            }
        }
    }
}

// ---------------------------------------------------------------------------
// Kernel 3: output projection. X = g_cx16. grid = (8, 64), 128 threads.
// ---------------------------------------------------------------------------
__global__ __launch_bounds__(128, 4)
void out_proj_tc(const float* __restrict__ bo, float* __restrict__ out) {
    extern __shared__ uint16_t gsm[];
    float acc[2][8][4];
#pragma unroll
    for (int mi = 0; mi < 2; mi++)
#pragma unroll
        for (int ni = 0; ni < 8; ni++)
#pragma unroll
            for (int r = 0; r < 4; r++) acc[mi][ni][r] = 0.f;

    const int m0 = blockIdx.y * 64;
    const int n0 = blockIdx.x * 128;
    gemm_tile(g_cx16, g_wo16, gsm, m0, n0, acc);

    const int tid  = threadIdx.x;
    const int warp = tid >> 5;
    const int lane = tid & 31;
    const int g = lane >> 2, t = lane & 3;
    const int wm = (warp & 1) * 32;
    const int wn = (warp >> 1) * 64;

#pragma unroll
    for (int mi = 0; mi < 2; mi++) {
#pragma unroll
        for (int rr = 0; rr < 2; rr++) {
            const int m = m0 + wm + mi * 16 + rr * 8 + g;
#pragma unroll
            for (int ni = 0; ni < 8; ni++) {
                const int n = n0 + wn + ni * 8 + t * 2;
                float2 v;
                v.x = acc[mi][ni][rr * 2 + 0] + bo[n];
                v.y = acc[mi][ni][rr * 2 + 1] + bo[n + 1];
                *(float2*)&out[(size_t)m * DD + n] = v;
            }
        }
    }
}

// ---------------------------------------------------------------------------
// Kernel 2: fp16 causal flash attention (final: R14 config + masked-warp skip).
// CTA = 128 q-rows x (head, batch), 8 warps x m16, KV tiles of 64.
// QK^T = q*(khi+klo); PV = p*v. On the diagonal tile, warps whose entire
// 16-row block is masked (q rows < k0) skip the tile body (exact no-op).
// Barriers/prefetch/wait stay outside the conditional.
// SMEM (144B rows): Q 0 / KH 18432 / KL 27648 / V 36864 (2 bufs)
// ---------------------------------------------------------------------------
#define FQ  0
#define FKH 18432
#define FKL 27648
#define FV  36864
#define FA_SMEM 55296

__global__ __launch_bounds__(256, 2)
void flash_attn_tc() {
    extern __shared__ char fsm[];
    const uint32_t sb = (uint32_t)__cvta_generic_to_shared(fsm);

    const int qt = (gridDim.x - 1) - blockIdx.x;  // heavy tiles first
    const int h  = blockIdx.y;
    const int b  = blockIdx.z;
    const int tid  = threadIdx.x;
    const int warp = tid >> 5;
    const int lane = tid & 31;
    const int g = lane >> 2;
    const int t = lane & 3;
    const int wm = warp * 16;
    const int q0 = qt * 128;

    const size_t hb = (size_t)(b * HH + h) * SS * HD;
    const uint16_t* __restrict__ Qg = g_fq  + hb;
    const uint16_t* __restrict__ Hg = g_fkh + hb;
    const uint16_t* __restrict__ Lg = g_fkl + hb;
    const uint16_t* __restrict__ Vg = g_fv  + hb;

    const int sel = lane >> 3;
    const int l7  = lane & 7;
    // A-frag (Q / P): sel&1 -> +8 rows, sel>>1 -> +16B k
    const uint32_t aOff = ((wm + (sel & 1) * 8 + l7) * 144) + (sel >> 1) * 16;
    const uint32_t qAddr = sb + FQ + aOff;
    // K B-frag: sel>>1 -> +8 n-rows, sel&1 -> +16B k
    const uint32_t kOff = (((sel >> 1) * 8 + l7) * 144) + (sel & 1) * 16;
    const uint32_t kAddrH = sb + FKH + kOff;
    const uint32_t kAddrL = sb + FKL + kOff;
    // V trans B-frag: sel&1 -> +8 k-rows, sel>>1 -> +16B n
    const uint32_t vBase = sb + FV + (((sel & 1) * 8 + l7) * 144) + (sel >> 1) * 16;

    // ---- prologue: K/V tile 0, then Q ----
    {
#pragma unroll
        for (int r = 0; r < 4; r++) {        // K hi+lo: 1024 chunks
            const int idx = tid + r * 256;
            const int plane = idx >> 9;
            const int rem = idx & 511;
            const int row = rem >> 3;
            const int c = (rem & 7) * 8;
            const uint16_t* src = plane ? Lg : Hg;
            cp_async16(fsm + (plane ? FKL : FKH) + row * 144 + c * 2,
                       src + (size_t)row * HD + c);
        }
#pragma unroll
        for (int r = 0; r < 2; r++) {        // V buf0: 512 chunks
            const int idx = tid + r * 256;
            const int row = idx >> 3;
            const int c = (idx & 7) * 8;
            cp_async16(fsm + FV + row * 144 + c * 2, Vg + (size_t)row * HD + c);
        }
        cp_commit();
#pragma unroll
        for (int r = 0; r < 4; r++) {        // Q: 1024 chunks
            const int idx = tid + r * 256;
            const int row = idx >> 3;
            const int c = (idx & 7) * 8;
            cp_async16(fsm + FQ + row * 144 + c * 2,
                       Qg + (size_t)(q0 + row) * HD + c);
        }
        cp_commit();
        asm volatile("cp.async.wait_group 0;\n");
    }
    __syncthreads();

    // pin Q fragments in registers: 4 k16-steps
    uint32_t qf[4][4];
#pragma unroll
    for (int ks = 0; ks < 4; ks++)
        ldsm4(qf[ks][0], qf[ks][1], qf[ks][2], qf[ks][3], qAddr + ks * 32);
    __syncthreads();   // Q smem dead; Ps may overwrite

    float oacc[8][4];
#pragma unroll
    for (int ni = 0; ni < 8; ni++)
#pragma unroll
        for (int r = 0; r < 4; r++) oacc[ni][r] = 0.f;
    float m0r = -1e30f, m1r = -1e30f, l0r = 0.f, l1r = 0.f;

    const float scale = 0.125f;
    const int ntiles = 2 * qt + 2;

    for (int tt = 0; tt < ntiles; tt++) {
        const int k0 = tt * 64;
        const int buf = tt & 1;
        // warp fully masked iff its highest q-row (q0+wm+15) < k0 (diagonal tile only)
        const bool active = (q0 + wm + 15) >= k0;

        // ---- S = q*(khi + klo) ----
        float sacc[8][4];
        if (active) {
#pragma unroll
            for (int ni = 0; ni < 8; ni++)
#pragma unroll
                for (int r = 0; r < 4; r++) sacc[ni][r] = 0.f;

#pragma unroll
            for (int ks = 0; ks < 4; ks++) {
                const uint32_t ko = ks * 32;
#pragma unroll
                for (int p = 0; p < 4; p++) {
                    uint32_t h0, h1, h2, h3, l0, l1, l2, l3;
                    ldsm4(h0, h1, h2, h3, kAddrH + p * 2304 + ko);
                    ldsm4(l0, l1, l2, l3, kAddrL + p * 2304 + ko);
                    mma_f16(sacc[2 * p],     qf[ks], h0, h1);
                    mma_f16(sacc[2 * p],     qf[ks], l0, l1);
                    mma_f16(sacc[2 * p + 1], qf[ks], h2, h3);
                    mma_f16(sacc[2 * p + 1], qf[ks], l2, l3);
                }
            }
        }
        __syncthreads();   // K readers done before prefetch overwrites

        // ---- prefetch K/V for tile tt+1 (overlaps softmax + PV) ----
        if (tt + 1 < ntiles) {
            const int kn = (tt + 1) * 64;
            const int nbuf = (tt + 1) & 1;
#pragma unroll
            for (int r = 0; r < 4; r++) {
                const int idx = tid + r * 256;
                const int plane = idx >> 9;
                const int rem = idx & 511;
                const int row = rem >> 3;
                const int c = (rem & 7) * 8;
                const uint16_t* src = plane ? Lg : Hg;
                cp_async16(fsm + (plane ? FKL : FKH) + row * 144 + c * 2,
                           src + (size_t)(kn + row) * HD + c);
            }
#pragma unroll
            for (int r = 0; r < 2; r++) {
                const int idx = tid + r * 256;
                const int row = idx >> 3;
                const int c = (idx & 7) * 8;
                cp_async16(fsm + FV + nbuf * 9216 + row * 144 + c * 2,
                           Vg + (size_t)(kn + row) * HD + c);
            }
            cp_commit();
        }

        if (active) {
            // ---- scale + causal mask (only last 2 tiles touch diagonal) ----
            const bool need_mask = (tt >= ntiles - 2);
            const int qi0 = q0 + wm + g;
            const int qi1 = qi0 + 8;
#pragma unroll
            for (int ni = 0; ni < 8; ni++) {
                const int c0 = k0 + ni * 8 + 2 * t;
                sacc[ni][0] *= scale; sacc[ni][1] *= scale;
                sacc[ni][2] *= scale; sacc[ni][3] *= scale;
                if (need_mask) {
                    if (c0 > qi0)     sacc[ni][0] -= 1e9f;
                    if (c0 + 1 > qi0) sacc[ni][1] -= 1e9f;
                    if (c0 > qi1)     sacc[ni][2] -= 1e9f;
                    if (c0 + 1 > qi1) sacc[ni][3] -= 1e9f;
                }
            }

            // ---- online softmax ----
            float mx0 = -1e30f, mx1 = -1e30f;
#pragma unroll
            for (int ni = 0; ni < 8; ni++) {
                mx0 = fmaxf(mx0, fmaxf(sacc[ni][0], sacc[ni][1]));
                mx1 = fmaxf(mx1, fmaxf(sacc[ni][2], sacc[ni][3]));
            }
            mx0 = fmaxf(mx0, __shfl_xor_sync(0xffffffffu, mx0, 1));
            mx0 = fmaxf(mx0, __shfl_xor_sync(0xffffffffu, mx0, 2));
            mx1 = fmaxf(mx1, __shfl_xor_sync(0xffffffffu, mx1, 1));
            mx1 = fmaxf(mx1, __shfl_xor_sync(0xffffffffu, mx1, 2));

            const float mn0 = fmaxf(m0r, mx0);
            const float mn1 = fmaxf(m1r, mx1);
            const float al0 = __expf(m0r - mn0);
            const float al1 = __expf(m1r - mn1);
            float s0 = 0.f, s1 = 0.f;
#pragma unroll
            for (int ni = 0; ni < 8; ni++) {
                float p0 = __expf(sacc[ni][0] - mn0);
                float p1 = __expf(sacc[ni][1] - mn0);
                float p2 = __expf(sacc[ni][2] - mn1);
                float p3 = __expf(sacc[ni][3] - mn1);
                s0 += p0 + p1; s1 += p2 + p3;
                const uint32_t cby = (uint32_t)(ni * 8 + 2 * t) * 2;
                *(uint32_t*)(fsm + FQ + (wm + g)     * 144 + cby) = fh2(p0, p1);
                *(uint32_t*)(fsm + FQ + (wm + g + 8) * 144 + cby) = fh2(p2, p3);
            }
            s0 += __shfl_xor_sync(0xffffffffu, s0, 1);
            s0 += __shfl_xor_sync(0xffffffffu, s0, 2);
            s1 += __shfl_xor_sync(0xffffffffu, s1, 1);
            s1 += __shfl_xor_sync(0xffffffffu, s1, 2);
            l0r = l0r * al0 + s0;
            l1r = l1r * al1 + s1;
            m0r = mn0; m1r = mn1;
#pragma unroll
            for (int ni = 0; ni < 8; ni++) {
                oacc[ni][0] *= al0; oacc[ni][1] *= al0;
                oacc[ni][2] *= al1; oacc[ni][3] *= al1;
            }
            __syncwarp();   // Ps rows per-warp: write->read within warp

            // ---- O += P @ V ----
#pragma unroll
            for (int ks = 0; ks < 4; ks++) {
                uint32_t pf[4];
                ldsm4(pf[0], pf[1], pf[2], pf[3], qAddr + ks * 32);
                const uint32_t vrow = vBase + buf * 9216 + ks * 2304;
#pragma unroll
                for (int p = 0; p < 4; p++) {
                    uint32_t v0, v1, v2, v3;
                    ldsm4t(v0, v1, v2, v3, vrow + p * 32);
                    mma_f16(oacc[2 * p],     pf, v0, v1);
                    mma_f16(oacc[2 * p + 1], pf, v2, v3);
                }
            }
        }
        if (tt + 1 < ntiles) asm volatile("cp.async.wait_group 0;\n");
        __syncthreads();   // publish next K/V; retire Ps/V reads
    }

    // ---- normalize + store ctx fp16 [B,S,D] ----
    const float inv0 = 1.0f / l0r;
    const float inv1 = 1.0f / l1r;
    const int r0 = q0 + wm + g;
    const size_t o0 = ((size_t)(b * SS + r0))     * DD + h * HD;
    const size_t o1 = ((size_t)(b * SS + r0 + 8)) * DD + h * HD;
#pragma unroll
    for (int ni = 0; ni < 8; ni++) {
        const int c = ni * 8 + 2 * t;
        *(uint32_t*)&g_cx16[o0 + c] = fh2(oacc[ni][0] * inv0, oacc[ni][1] * inv0);
        *(uint32_t*)&g_cx16[o1 + c] = fh2(oacc[ni][2] * inv1, oacc[ni][3] * inv1);
    }
}

// ---------------------------------------------------------------------------
extern "C" void kernel_launch(void* const* d_in, const int* in_sizes, int n_in,
                              void* d_out, int out_size) {
    const float* query = (const float*)d_in[0];
    const float* key   = (const float*)d_in[1];
    const float* value = (const float*)d_in[2];
    // d_in[3] = mask (causal; applied analytically in-kernel)
    const float* Wq = (const float*)d_in[4];
    const float* bq = (const float*)d_in[5];
    const float* Wk = (const float*)d_in[6];
    const float* bk = (const float*)d_in[7];
    const float* Wv = (const float*)d_in[8];
    const float* bv = (const float*)d_in[9];
    const float* Wo = (const float*)d_in[10];
    const float* bo = (const float*)d_in[11];
    float* out = (float*)d_out;

    cudaFuncSetAttribute(flash_attn_tc,
                         cudaFuncAttributeMaxDynamicSharedMemorySize, FA_SMEM);
    cudaFuncSetAttribute(qkv_proj_tc,
                         cudaFuncAttributeMaxDynamicSharedMemorySize, PJ_SMEM);
    cudaFuncSetAttribute(out_proj_tc,
                         cudaFuncAttributeMaxDynamicSharedMemorySize, PJ_SMEM);

    dim3 gcvt(512, 7);
    cvt_f16_all<<<gcvt, 256>>>(query, key, value, Wq, Wk, Wv, Wo);

    dim3 gproj(DD / 128, MM / 64, 3);
    qkv_proj_tc<<<gproj, 128, PJ_SMEM>>>(bq, bk, bv);

    dim3 gfa(SS / 128, HH, BB);
    flash_attn_tc<<<gfa, 256, FA_SMEM>>>();

    dim3 gout(DD / 128, MM / 64);
    out_proj_tc<<<gout, 128, PJ_SMEM>>>(bo, out);
}